// round 16
// baseline (speedup 1.0000x reference)
#include <cuda_runtime.h>

#define Bn  2
#define Sn  192
#define Dn  128
#define DIN 1024
#define BSn (Bn*Sn)                       // 384 rows
#define SZo ((long)Bn*Sn*Sn*Sn)           // elements per output tensor

// engine geometry
#define MT 192
#define NT 64
#define KC 16
#define PA 392                            // dup-A pitch (2*192 + 8), 16B-aligned rows
#define PB 68

typedef unsigned long long ull;
union F4U { float4 f; ull u[2]; };

__device__ __forceinline__ ull ffma2(ull a, ull b, ull c) {
    ull d;
    asm("fma.rn.f32x2 %0, %1, %2, %3;" : "=l"(d) : "l"(a), "l"(b), "l"(c));
    return d;
}

// ---- scratch (device globals: allocation-free contract) ----
__device__ float g_mlp[3*BSn*Dn];         // p, sh, st
__device__ float g_wz[BSn*Dn*Dn];         // wz / u scratch
__device__ float g_t [BSn*Sn*Dn];         // t  / v scratch

// ============================================================================
// MLP: C = leaky_relu(x @ W + b), 64x64 tiles, K=1024. grid(6,2,3)  (tiny)
// ============================================================================
__global__ __launch_bounds__(256) void mlp_kernel(
    const float* __restrict__ x,
    const float* __restrict__ W0, const float* __restrict__ b0,
    const float* __restrict__ W1, const float* __restrict__ b1,
    const float* __restrict__ W2, const float* __restrict__ b2)
{
    const int mt = blockIdx.x, nt = blockIdx.y, w = blockIdx.z;
    const float* W    = (w == 0) ? W0 : (w == 1) ? W1 : W2;
    const float* bias = (w == 0) ? b0 : (w == 1) ? b1 : b2;
    float* C = g_mlp + (long)w * BSn * Dn;

    __shared__ float As[64][17];
    __shared__ float Bs[16][65];
    const int tid = threadIdx.x;
    const int tx = tid & 15, ty = tid >> 4;
    const int m0 = mt * 64, n0 = nt * 64;
    float acc[4][4] = {};

    for (int k0 = 0; k0 < DIN; k0 += 16) {
        {
            int mm = tid >> 2, kk = (tid & 3) << 2;
            float4 v = *(const float4*)(x + (long)(m0 + mm) * DIN + k0 + kk);
            As[mm][kk] = v.x; As[mm][kk+1] = v.y; As[mm][kk+2] = v.z; As[mm][kk+3] = v.w;
        }
        {
            int kk = tid >> 4, nn = (tid & 15) << 2;
            float4 v = *(const float4*)(W + (long)(k0 + kk) * Dn + n0 + nn);
            Bs[kk][nn] = v.x; Bs[kk][nn+1] = v.y; Bs[kk][nn+2] = v.z; Bs[kk][nn+3] = v.w;
        }
        __syncthreads();
        #pragma unroll
        for (int kk = 0; kk < 16; kk++) {
            float a[4], b[4];
            #pragma unroll
            for (int r = 0; r < 4; r++) a[r] = As[ty*4 + r][kk];
            #pragma unroll
            for (int c = 0; c < 4; c++) b[c] = Bs[kk][tx + 16*c];
            #pragma unroll
            for (int r = 0; r < 4; r++)
                #pragma unroll
                for (int c = 0; c < 4; c++) acc[r][c] = fmaf(a[r], b[c], acc[r][c]);
        }
        __syncthreads();
    }
    #pragma unroll
    for (int r = 0; r < 4; r++) {
        int m = m0 + ty*4 + r;
        #pragma unroll
        for (int c = 0; c < 4; c++) {
            int n = n0 + tx + 16*c;
            float v = acc[r][c] + bias[n];
            v = (v > 0.f) ? v : 0.1f * v;
            C[(long)m * Dn + n] = v;
        }
    }
}

// ============================================================================
// FFMA2 engine v3: 192x64 tile, 256 threads, 12x4 micro, K=128, k-chunk 16.
// A stored duplicated (As[k][2m]=As[k][2m+1]): reads are pure broadcast
// (2 distinct addrs per warp per LDS.128).  Per k-step per thread:
// 6x LDS.128 (A) + 1x LDS.128 (B) + 24x fma.rn.f32x2 (48 FMA).
// A-staging: one smem row per STS instr, consecutive cols -> conflict-free.
// ============================================================================
__device__ __forceinline__ void ml192(
    ull acc[12][2], float (*As)[PA], float (*Bs)[PB],
    const float* __restrict__ Ab, const float* __restrict__ Bb,
    int lda, int ldb, int n0, int bT, int tid, int tx, int ty)
{
    const int k4 = tid >> 6;              // 0..3 : which group of 4 k's
    const int mA = tid & 63;              // base m; rows mA, mA+64, mA+128
    const float* aLd = Ab + (long)mA * lda + k4 * 4;

    int bk, bn;
    const float* bLd;
    if (!bT) { bk = tid >> 4; bn = (tid & 15) * 4; bLd = Bb + (long)bk * ldb + n0 + bn; }
    else     { bn = tid >> 2; bk = (tid & 3) * 4;  bLd = Bb + (long)(n0 + bn) * ldb + bk; }

    float4 ra0 = *(const float4*)(aLd);
    float4 ra1 = *(const float4*)(aLd + 64 * lda);
    float4 ra2 = *(const float4*)(aLd + 128 * lda);
    float4 rb  = *(const float4*)(bLd);

    const int nIter = 128 / KC;           // 8
    for (int it = 0; it < nIter; it++) {
        // ---- stage A (dup) ----
        {
            float a0[4] = {ra0.x, ra0.y, ra0.z, ra0.w};
            float a1[4] = {ra1.x, ra1.y, ra1.z, ra1.w};
            float a2[4] = {ra2.x, ra2.y, ra2.z, ra2.w};
            #pragma unroll
            for (int i = 0; i < 4; i++) {
                *(float2*)&As[k4*4+i][2*mA]         = make_float2(a0[i], a0[i]);
                *(float2*)&As[k4*4+i][2*(mA+64)]    = make_float2(a1[i], a1[i]);
                *(float2*)&As[k4*4+i][2*(mA+128)]   = make_float2(a2[i], a2[i]);
            }
        }
        // ---- stage B ----
        if (!bT) {
            *(float4*)&Bs[bk][bn] = rb;
        } else {
            Bs[bk+0][bn] = rb.x; Bs[bk+1][bn] = rb.y;
            Bs[bk+2][bn] = rb.z; Bs[bk+3][bn] = rb.w;
        }
        __syncthreads();

        // ---- prefetch next chunk ----
        if (it + 1 < nIter) {
            aLd += KC;
            ra0 = *(const float4*)(aLd);
            ra1 = *(const float4*)(aLd + 64 * lda);
            ra2 = *(const float4*)(aLd + 128 * lda);
            bLd += bT ? KC : (long)KC * ldb;
            rb = *(const float4*)(bLd);
        }

        // ---- compute ----
        #pragma unroll
        for (int kk = 0; kk < KC; kk++) {
            F4U a[6], b;
            #pragma unroll
            for (int j = 0; j < 6; j++)
                a[j].f = *(const float4*)&As[kk][ty*24 + j*4];
            b.f = *(const float4*)&Bs[kk][tx*4];
            #pragma unroll
            for (int r = 0; r < 12; r++) {
                ull ap = a[r >> 1].u[r & 1];
                acc[r][0] = ffma2(ap, b.u[0], acc[r][0]);
                acc[r][1] = ffma2(ap, b.u[1], acc[r][1]);
            }
        }
        __syncthreads();
    }
}

// Generic batched GEMM (direct C write).  grid(M/192, N/64, batch), 256 thr.
__global__ __launch_bounds__(256, 2) void gemm192_kernel(
    const float* __restrict__ A, const float* __restrict__ Bm, float* __restrict__ C,
    int lda, int ldb, int ldc,
    int aDiv, long aStride, long bStride, long cStride, int bT)
{
    const int mt = blockIdx.x, nt = blockIdx.y, z = blockIdx.z;
    const float* Ab = A + (long)(z / aDiv) * aStride + (long)(mt * MT) * lda;
    const float* Bb = Bm + (long)z * bStride;
    float* Cb = C + (long)z * cStride;
    const int n0 = nt * NT;
    const int tid = threadIdx.x, tx = tid & 15, ty = tid >> 4;

    __shared__ float As[KC][PA];
    __shared__ float Bs[KC][PB];
    ull acc[12][2] = {};

    ml192(acc, As, Bs, Ab, Bb, lda, ldb, n0, bT, tid, tx, ty);

    #pragma unroll
    for (int r = 0; r < 12; r++) {
        F4U o; o.u[0] = acc[r][0]; o.u[1] = acc[r][1];
        *(float4*)(Cb + (long)(mt*MT + ty*12 + r) * ldc + n0 + tx*4) = o.f;
    }
}

// ============================================================================
// Output GEMM (NT): s[q][x,y] = sum_k A[q][x,k] * Y[b][y,k].  M=Sn, N strip=64.
// grid(3, BSn).  sym=0: direct full write of the 192x64 strip.
// sym=1: write upper part of strip (with in-diag mirror select) + mirror band
// rows (transposed) -- 2-pass Cs staging (rows [0,128) then [128,192)), Cs
// unioned over the A-tile buffer.  Diag blocks never straddle the 128 split.
// ============================================================================
__global__ __launch_bounds__(256, 2) void out192_kernel(
    const float* __restrict__ A, const float* __restrict__ Y,
    float* __restrict__ Out, int sym)
{
    const int by = blockIdx.x, q = blockIdx.y;
    const float* Ab = A + (long)q * (Sn * Dn);
    const float* Bb = Y + (long)(q / Sn) * (Sn * Dn);
    float* Ob = Out + (long)q * (Sn * Sn);
    const int n0 = by * NT;
    const int tid = threadIdx.x, tx = tid & 15, ty = tid >> 4;

    __shared__ __align__(16) char smem_u[128 * PB * 4];   // 34816B: As (25088) / Cs union
    __shared__ float Bs[KC][PB];
    float (*As)[PA] = (float(*)[PA])smem_u;
    float (*Cs)[PB] = (float(*)[PB])smem_u;

    ull acc[12][2] = {};
    ml192(acc, As, Bs, Ab, Bb, Dn, Dn, n0, /*bT=*/1, tid, tx, ty);

    if (!sym) {
        #pragma unroll
        for (int r = 0; r < 12; r++) {
            F4U o; o.u[0] = acc[r][0]; o.u[1] = acc[r][1];
            *(float4*)&Ob[(long)(ty*12 + r) * Sn + n0 + tx*4] = o.f;
        }
        return;
    }

    // ---- symmetric epilogue: 2 passes over row ranges [0,128), [128,192) ----
    for (int h = 0; h < 2; h++) {
        const int rbase = 128 * h;
        const int rcnt  = h ? 64 : 128;
        // stage this pass's rows
        #pragma unroll
        for (int r = 0; r < 12; r++) {
            int g = ty*12 + r;
            if (g >= rbase && g < rbase + rcnt) {
                F4U o; o.u[0] = acc[r][0]; o.u[1] = acc[r][1];
                *(float4*)&Cs[g - rbase][tx*4] = o.f;
            }
        }
        __syncthreads();

        // strip part: rows [rbase, min(n0+64, rbase+rcnt)), cols [n0, n0+64)
        {
            int sHi = n0 + 64 < rbase + rcnt ? n0 + 64 : rbase + rcnt;
            const int c0 = n0 + tx*4;
            for (int row = rbase + (tid >> 4); row < sHi; row += 16) {
                int rl = row - rbase;
                float4 v;
                if (row < n0) {
                    v = *(float4*)&Cs[rl][tx*4];
                } else {
                    // diag block: per-lane upper/mirror select (diag is in-pass)
                    float vi[4];
                    #pragma unroll
                    for (int i = 0; i < 4; i++) {
                        int c = c0 + i;
                        vi[i] = (row <= c) ? Cs[rl][tx*4 + i]
                                           : Cs[c - rbase][row - n0];
                    }
                    v = make_float4(vi[0], vi[1], vi[2], vi[3]);
                }
                *(float4*)&Ob[(long)row * Sn + c0] = v;
            }
        }

        // band part (pass 0 only): rows y in [n0, n0+64), cols x in [0, n0)
        if (h == 0 && n0 > 0) {
            #pragma unroll
            for (int yy = 0; yy < 4; yy++) {
                int y  = n0 + yy*16 + (tid >> 4);
                int yl = y - n0;
                for (int x4 = tx*4; x4 < n0; x4 += 64) {
                    float vi[4];
                    #pragma unroll
                    for (int ii = 0; ii < 4; ii++) {
                        int i = (ii + tx) & 3;            // bank-rotated gather
                        vi[i] = Cs[x4 + i][yl];
                    }
                    *(float4*)&Ob[(long)y * Sn + x4] =
                        make_float4(vi[0], vi[1], vi[2], vi[3]);
                }
            }
        }
        __syncthreads();
    }
}

// ============================================================================
// pt_cop mirror pass over output layout [b,x,y,z]: for x>y, out[b,x,y,:] = out[b,y,x,:]
// ============================================================================
__global__ void mirror_kernel(float* __restrict__ Out)
{
    const int x = blockIdx.x, b = blockIdx.y;
    for (int y = 0; y < x; y++) {
        long dst = ((long)(b * Sn + x) * Sn + y) * Sn;
        long src = ((long)(b * Sn + y) * Sn + x) * Sn;
        for (int z = threadIdx.x; z < Sn; z += blockDim.x)
            Out[dst + z] = Out[src + z];
    }
}

// ============================================================================
extern "C" void kernel_launch(void* const* d_in, const int* in_sizes, int n_in,
                              void* d_out, int out_size)
{
    const float* x  = (const float*)d_in[0];
    const float* Wp = (const float*)d_in[1];
    const float* bp = (const float*)d_in[2];
    const float* Wh = (const float*)d_in[3];
    const float* bh = (const float*)d_in[4];
    const float* Wt = (const float*)d_in[5];
    const float* bt = (const float*)d_in[6];
    const float* W_span_ph = (const float*)d_in[7];
    const float* W_span_pt = (const float*)d_in[8];
    const float* W_ph_sib  = (const float*)d_in[9];
    const float* W_pt_sib  = (const float*)d_in[10];
    const float* W_ph_cop  = (const float*)d_in[11];
    const float* W_pt_cop  = (const float*)d_in[12];
    float* out = (float*)d_out;

    float *mlpP, *wzP, *tP;
    cudaGetSymbolAddress((void**)&mlpP, g_mlp);
    cudaGetSymbolAddress((void**)&wzP,  g_wz);
    cudaGetSymbolAddress((void**)&tP,   g_t);
    const float* p  = mlpP;
    const float* sh = mlpP + BSn * Dn;
    const float* st = mlpP + 2 * BSn * Dn;

    // p, sh, st
    mlp_kernel<<<dim3(6, 2, 3), 256>>>(x, Wp, bp, Wh, bh, Wt, bt);

    // ---- type 1 (sym, layout [b,z,x,y]): span_psh, span_pst, ph_sib, pt_sib ----
    const float* Ws1[4] = {W_span_ph, W_span_pt, W_ph_sib, W_pt_sib};
    const float* Xs1[4] = {sh, sh, sh, st};
    const float* Ys1[4] = {st, st, sh, st};
    for (int t = 0; t < 4; t++) {
        // wz[r, i, j] = sum_k p[r,k] * w[i,k,j]   (batch over i)
        gemm192_kernel<<<dim3(2, 2, 128), 256>>>(p, Ws1[t], wzP,
            Dn, Dn, Dn*Dn, 1, 0L, (long)Dn*Dn, (long)Dn, 0);
        // t[q, x, j] = sum_i X[b,x,i] * wz[q,i,j]  (NN, batch over q=(b,z))
        gemm192_kernel<<<dim3(1, 2, 384), 256>>>(Xs1[t], wzP, tP,
            Dn, Dn, Dn, Sn, (long)Sn*Dn, (long)Dn*Dn, (long)Sn*Dn, 0);
        // s[q, x, y] = sum_j t[q,x,j] * Y[b,y,j]   (NT, symmetrized write)
        out192_kernel<<<dim3(3, 384), 256>>>(tP, Ys1[t], out + (long)t * SZo, 1);
    }

    // ---- type 2 (co-parent, layout [b,x,y,z]): ph_cop, pt_cop ----
    const float* Ws2[2] = {W_ph_cop, W_pt_cop};
    const float* Zs2[2] = {sh, st};
    for (int t = 0; t < 2; t++) {
        // u[r, k, j] = sum_i p[r,i] * w[i,k,j]    (batch over k)
        gemm192_kernel<<<dim3(2, 2, 128), 256>>>(p, Ws2[t], wzP,
            Dn, Dn*Dn, Dn*Dn, 1, 0L, (long)Dn, (long)Dn, 0);
        // v[q, y, k] = sum_j p[b,y,j] * u[q,k,j]  (NT, batch over q=(b,x))
        gemm192_kernel<<<dim3(1, 2, 384), 256>>>(p, wzP, tP,
            Dn, Dn, Dn, Sn, (long)Sn*Dn, (long)Dn*Dn, (long)Sn*Dn, 1);
        // out[q, y, z] = sum_k v[q,y,k] * Z[b,z,k] (NT, full write, z contiguous)
        out192_kernel<<<dim3(3, 384), 256>>>(tP, Zs2[t], out + (long)(4 + t) * SZo, 0);
    }
    // pt_cop: sym over (x,y) crosses batch planes -> mirror pass
    mirror_kernel<<<dim3(Sn, Bn), 192>>>(out + 5 * SZo);
}